// round 15
// baseline (speedup 1.0000x reference)
#include <cuda_runtime.h>
#include <cuda_fp16.h>
#include <math.h>
#include <stdint.h>

#define NTOK   131072
#define NCODE  2048
#define DIM    64
#define NCAND  32
#define MARGIN 8e-3f

// Output layout (tuple flattened):
#define OFF_XOUT   0
#define OFF_COMMIT 8388608
#define OFF_PERP   8388609
#define OFF_NCB    8388610
#define OFF_NSUM   8519682
#define OFF_NCNT   8650754

// ---- device scratch ----
__device__ int   g_idx[NTOK];
__device__ int   g_hist[NCODE];
__device__ int   g_start[NCODE];
__device__ int   g_cursor[NCODE];
__device__ int   g_tok[NTOK];
__device__ float g_cnorm[NCODE];
__device__ float g_sumb[NCODE * DIM];
__device__ float g_commit;
__device__ float g_plog;
__device__ __half g_ch[NCODE * DIM];
__device__ int   g_cand[(size_t)NTOK * NCAND];
__device__ float g_candt[(size_t)NTOK * NCAND];
__device__ int   g_candn[NTOK];
__device__ float g_tmin[NTOK];

__device__ __forceinline__ uint32_t smem_u32(const void* p) {
    uint32_t a;
    asm("{ .reg .u64 t; cvta.to.shared.u64 t, %1; cvt.u32.u64 %0, t; }" : "=r"(a) : "l"(p));
    return a;
}
#define LDX4(r, addr) \
    asm volatile("ldmatrix.sync.aligned.m8n8.x4.shared.b16 {%0,%1,%2,%3}, [%4];" \
        : "=r"((r)[0]), "=r"((r)[1]), "=r"((r)[2]), "=r"((r)[3]) : "r"(addr))

__device__ __forceinline__ void mma16816(float* c, const uint32_t* a, uint32_t b0, uint32_t b1) {
    asm volatile("mma.sync.aligned.m16n8k16.row.col.f32.f16.f16.f32 "
        "{%0,%1,%2,%3},{%4,%5,%6,%7},{%8,%9},{%0,%1,%2,%3};"
        : "+f"(c[0]), "+f"(c[1]), "+f"(c[2]), "+f"(c[3])
        : "r"(a[0]), "r"(a[1]), "r"(a[2]), "r"(a[3]), "r"(b0), "r"(b1));
}
__device__ __forceinline__ void cpa16(uint32_t dst, const void* src) {
    asm volatile("cp.async.cg.shared.global [%0], [%1], 16;" :: "r"(dst), "l"(src));
}
#define CPA_COMMIT() asm volatile("cp.async.commit_group;" ::: "memory")
#define CPA_WAIT1()  asm volatile("cp.async.wait_group 1;" ::: "memory")

union U8H { __half h[8]; uint4 u; };
union U4H { __half h[4]; uint2 u; };

// smem per buffer: bh[128 rows * 144B] + cns[128]f
#define OFF_CN 18432
#define BUFB   18944

// ---- K0: zero scalars + histogram ----
__global__ void k_zero() {
    int i = blockIdx.x * 256 + threadIdx.x;
    if (i < NCODE) g_hist[i] = 0;
    if (i == 0) { g_commit = 0.0f; g_plog = 0.0f; }
}

// ---- K0b: codebook fp16-high + ||c||^2 (reference rounding) ----
__global__ void k_split_cb(const float* __restrict__ cb) {
    int c = blockIdx.x * 256 + threadIdx.x;
    if (c >= NCODE) return;
    const float4* cp = (const float4*)(cb + (size_t)c * DIM);
    float cn = 0.0f;
#pragma unroll
    for (int q = 0; q < 8; q++) {
        float4 a = cp[2 * q], b = cp[2 * q + 1];
        float v[8] = {a.x, a.y, a.z, a.w, b.x, b.y, b.z, b.w};
        U8H H;
#pragma unroll
        for (int i = 0; i < 8; i++) {
            H.h[i] = __float2half_rn(v[i]);
            cn = __fadd_rn(cn, __fmul_rn(v[i], v[i]));
        }
        *(uint4*)&g_ch[(size_t)c * DIM + q * 8] = H.u;
    }
    g_cnorm[c] = cn;
}

// ---- K1: hh-only HMMA scan + candidate recording ----
__device__ __forceinline__ void prefetch_chunk(uint32_t bsm, int n0, int tid) {
#pragma unroll
    for (int i = tid; i < 1024; i += 256) {
        int r = i >> 3, j = i & 7;
        cpa16(bsm + r * 144 + j * 16, &g_ch[(size_t)(n0 + r) * DIM + j * 8]);
    }
    if (tid < 32) cpa16(bsm + OFF_CN + tid * 16, &g_cnorm[n0 + tid * 4]);
}

__global__ void __launch_bounds__(256, 2) k1_scan(const float* __restrict__ x) {
    __shared__ __align__(16) char buf[2 * BUFB];
    __shared__ int scnt[128];
    uint32_t sb = smem_u32(buf);
    int tid = threadIdx.x, w = tid >> 5, l = tid & 31;
    int g = l >> 3, lr = l & 7, gid = l >> 2, tig = l & 3;
    int m0 = blockIdx.x * 128;

    if (tid < 128) scnt[tid] = 0;

    // convert x rows to fp16-high into buf0 (stride 144)
    {
        int r = tid >> 1, seg = tid & 1;
        const float4* xp = (const float4*)(x + (size_t)(m0 + r) * DIM + seg * 32);
#pragma unroll
        for (int q = 0; q < 8; q++) {
            float4 v = xp[q];
            U4H H;
            H.h[0] = __float2half_rn(v.x); H.h[1] = __float2half_rn(v.y);
            H.h[2] = __float2half_rn(v.z); H.h[3] = __float2half_rn(v.w);
            *(uint2*)(buf + r * 144 + (seg * 32 + q * 4) * 2) = H.u;
        }
    }
    __syncthreads();

    uint32_t ah[4][4];
    {
        int arow = w * 16 + (g & 1) * 8 + lr;
#pragma unroll
        for (int kk = 0; kk < 4; kk++)
            LDX4(ah[kk], sb + arow * 144 + (kk * 16 + (g >> 1) * 8) * 2);
    }
    __syncthreads();

    int tokl0 = w * 16 + gid, tokl1 = tokl0 + 8;
    int tokg0 = m0 + tokl0, tokg1 = m0 + tokl1;
    float tmin0 = 3.4e38f, tmin1 = 3.4e38f;
    float thr0 = 3.4e38f, thr1 = 3.4e38f;

    prefetch_chunk(sb, 0, tid);          CPA_COMMIT();
    prefetch_chunk(sb + BUFB, 128, tid); CPA_COMMIT();

    for (int c = 0; c < 16; c++) {
        uint32_t bb = sb + (c & 1) * BUFB;
        const float* cns = (const float*)(buf + (c & 1) * BUFB + OFF_CN);
        CPA_WAIT1();
        __syncthreads();

#pragma unroll
        for (int hf = 0; hf < 2; hf++) {
            float acc[8][4];
#pragma unroll
            for (int n = 0; n < 8; n++)
#pragma unroll
                for (int q = 0; q < 4; q++) acc[n][q] = 0.0f;

#pragma unroll
            for (int kk = 0; kk < 4; kk++) {
#pragma unroll
                for (int p = 0; p < 4; p++) {
                    int brow = hf * 64 + p * 16 + (g & 1) * 8 + lr;
                    uint32_t bh[4];
                    LDX4(bh, bb + brow * 144 + (kk * 16 + (g >> 1) * 8) * 2);
                    mma16816(acc[2 * p],     ah[kk], bh[0], bh[2]);
                    mma16816(acc[2 * p + 1], ah[kk], bh[1], bh[3]);
                }
            }
            // approximate epilogue: t = cn - 2*dot_hh; record candidates
#pragma unroll
            for (int nt = 0; nt < 8; nt++) {
                int nl = hf * 64 + nt * 8 + 2 * tig;
                float cn0 = cns[nl], cn1 = cns[nl + 1];
                int ci = c * 128 + nl;
                float t0 = __fmaf_rn(-2.0f, acc[nt][0], cn0);
                float t1 = __fmaf_rn(-2.0f, acc[nt][1], cn1);
                float t2 = __fmaf_rn(-2.0f, acc[nt][2], cn0);
                float t3 = __fmaf_rn(-2.0f, acc[nt][3], cn1);
                bool p = (t0 < thr0) | (t1 < thr0) | (t2 < thr1) | (t3 < thr1);
                if (__any_sync(0xffffffffu, p)) {
                    if (t0 < thr0) {
                        int pos = atomicAdd(&scnt[tokl0], 1);
                        if (pos < NCAND) { g_cand[(size_t)tokg0 * NCAND + pos] = ci;
                                           g_candt[(size_t)tokg0 * NCAND + pos] = t0; }
                        if (t0 < tmin0) { tmin0 = t0; thr0 = tmin0 + MARGIN; }
                    }
                    if (t1 < thr0) {
                        int pos = atomicAdd(&scnt[tokl0], 1);
                        if (pos < NCAND) { g_cand[(size_t)tokg0 * NCAND + pos] = ci + 1;
                                           g_candt[(size_t)tokg0 * NCAND + pos] = t1; }
                        if (t1 < tmin0) { tmin0 = t1; thr0 = tmin0 + MARGIN; }
                    }
                    if (t2 < thr1) {
                        int pos = atomicAdd(&scnt[tokl1], 1);
                        if (pos < NCAND) { g_cand[(size_t)tokg1 * NCAND + pos] = ci;
                                           g_candt[(size_t)tokg1 * NCAND + pos] = t2; }
                        if (t2 < tmin1) { tmin1 = t2; thr1 = tmin1 + MARGIN; }
                    }
                    if (t3 < thr1) {
                        int pos = atomicAdd(&scnt[tokl1], 1);
                        if (pos < NCAND) { g_cand[(size_t)tokg1 * NCAND + pos] = ci + 1;
                                           g_candt[(size_t)tokg1 * NCAND + pos] = t3; }
                        if (t3 < tmin1) { tmin1 = t3; thr1 = tmin1 + MARGIN; }
                    }
                }
            }
        }
        // quad-share running min to tighten thresholds
#pragma unroll
        for (int off = 1; off <= 2; off <<= 1) {
            tmin0 = fminf(tmin0, __shfl_xor_sync(0xffffffffu, tmin0, off));
            tmin1 = fminf(tmin1, __shfl_xor_sync(0xffffffffu, tmin1, off));
        }
        thr0 = tmin0 + MARGIN;
        thr1 = tmin1 + MARGIN;
        __syncthreads();
        if (c + 2 < 16) prefetch_chunk(bb, (c + 2) * 128, tid);
        CPA_COMMIT();
    }

    if (tig == 0) {
        g_tmin[tokg0]  = tmin0;
        g_tmin[tokg1]  = tmin1;
        g_candn[tokg0] = scnt[tokl0];
        g_candn[tokg1] = scnt[tokl1];
    }
}

// ---- K1b: exact refinement (1 warp per token) ----
__global__ void k_refine(const float* __restrict__ x, const float* __restrict__ cb) {
    int t = blockIdx.x * 8 + (threadIdx.x >> 5);
    int l = threadIdx.x & 31;
    int n = g_candn[t];
    float tmin = g_tmin[t];

    float2 xv = *(const float2*)(x + (size_t)t * DIM + l * 2);
    float lxn = __fadd_rn(__fmul_rn(xv.x, xv.x), __fmul_rn(xv.y, xv.y));
#pragma unroll
    for (int o = 16; o; o >>= 1) lxn += __shfl_xor_sync(0xffffffffu, lxn, o);
    float xn = lxn;

    float bv = 3.4e38f;
    int bi = NCODE;

    if (n <= NCAND) {
        for (int i = 0; i < n; i++) {
            float tv = g_candt[(size_t)t * NCAND + i];
            if (tv <= tmin + MARGIN) {
                int ci = g_cand[(size_t)t * NCAND + i];
                float2 cv = *(const float2*)(cb + (size_t)ci * DIM + l * 2);
                float d = __fmaf_rn(xv.y, cv.y, __fmul_rn(xv.x, cv.x));
#pragma unroll
                for (int o = 16; o; o >>= 1) d += __shfl_xor_sync(0xffffffffu, d, o);
                float s = __fadd_rn(__fsub_rn(xn, __fmul_rn(2.0f, d)), g_cnorm[ci]);
                if (s < bv || (s == bv && ci < bi)) { bv = s; bi = ci; }
            }
        }
    } else {
        for (int ci = 0; ci < NCODE; ci++) {
            float2 cv = *(const float2*)(cb + (size_t)ci * DIM + l * 2);
            float d = __fmaf_rn(xv.y, cv.y, __fmul_rn(xv.x, cv.x));
#pragma unroll
            for (int o = 16; o; o >>= 1) d += __shfl_xor_sync(0xffffffffu, d, o);
            float s = __fadd_rn(__fsub_rn(xn, __fmul_rn(2.0f, d)), g_cnorm[ci]);
            if (s < bv) { bv = s; bi = ci; }
        }
    }
    if (l == 0) g_idx[t] = bi;
}

// ---- K2a: histogram ----
__global__ void k_hist() {
    int t = blockIdx.x * 256 + threadIdx.x;
    atomicAdd(&g_hist[g_idx[t]], 1);
}

// ---- K2b: exclusive prefix scan (1 block) ----
__global__ void k_prefix() {
    __shared__ int warpsum[8];
    int tid = threadIdx.x, lane = tid & 31, wid = tid >> 5;
    int loc[8], s = 0;
#pragma unroll
    for (int j = 0; j < 8; j++) { loc[j] = s; s += g_hist[tid * 8 + j]; }
    int v = s;
#pragma unroll
    for (int off = 1; off < 32; off <<= 1) {
        int t = __shfl_up_sync(0xffffffffu, v, off);
        if (lane >= off) v += t;
    }
    if (lane == 31) warpsum[wid] = v;
    __syncthreads();
    if (wid == 0) {
        int wv = (lane < 8) ? warpsum[lane] : 0;
#pragma unroll
        for (int off = 1; off < 8; off <<= 1) {
            int t = __shfl_up_sync(0xffffffffu, wv, off);
            if (lane >= off) wv += t;
        }
        if (lane < 8) warpsum[lane] = wv;
    }
    __syncthreads();
    int base = ((wid > 0) ? warpsum[wid - 1] : 0) + (v - s);
#pragma unroll
    for (int j = 0; j < 8; j++) {
        g_start[tid * 8 + j]  = base + loc[j];
        g_cursor[tid * 8 + j] = base + loc[j];
    }
}

// ---- K2c: place tokens in code order ----
__global__ void k_place() {
    int t = blockIdx.x * 256 + threadIdx.x;
    int pos = atomicAdd(&g_cursor[g_idx[t]], 1);
    g_tok[pos] = t;
}

// ---- K2d: per-code gather-sum: code_sum_batch, x_out, commit ----
__global__ void k_sum(const float* __restrict__ x, const float* __restrict__ cb,
                      float* __restrict__ out) {
    int wid = threadIdx.x >> 5, l = threadIdx.x & 31;
    int c = blockIdx.x * 8 + wid;
    int d0 = l * 2;
    float cv0 = cb[(size_t)c * DIM + d0], cv1 = cb[(size_t)c * DIM + d0 + 1];
    int beg = g_start[c], n = g_hist[c];
    float s0 = 0.0f, s1 = 0.0f, cs = 0.0f;
    for (int i = 0; i < n; i++) {
        int t = g_tok[beg + i];
        float2 xv = *(const float2*)(x + (size_t)t * DIM + d0);
        float2 o;
        o.x = __fadd_rn(xv.x, __fsub_rn(cv0, xv.x));
        o.y = __fadd_rn(xv.y, __fsub_rn(cv1, xv.y));
        *(float2*)(out + OFF_XOUT + (size_t)t * DIM + d0) = o;
        s0 += xv.x; s1 += xv.y;
        float dx = __fsub_rn(xv.x, cv0), dy = __fsub_rn(xv.y, cv1);
        cs += dx * dx + dy * dy;
    }
    g_sumb[(size_t)c * DIM + d0]     = s0;
    g_sumb[(size_t)c * DIM + d0 + 1] = s1;
#pragma unroll
    for (int o = 16; o; o >>= 1) cs += __shfl_xor_sync(0xffffffffu, cs, o);
    if (l == 0) atomicAdd(&g_commit, cs);
}

// ---- K3: EMA update, new codebook, perplexity partials ----
__global__ void k_final(const float* __restrict__ x, const float* __restrict__ code_sum,
                        const float* __restrict__ code_count, float* __restrict__ out) {
    int i = blockIdx.x * 256 + threadIdx.x;
    int c = i >> 6, d = i & 63;
    float cntb = (float)g_hist[c];
    float ncnt = 0.99f * code_count[c] + 0.01f * cntb;
    float ns = 0.99f * code_sum[i] + 0.01f * g_sumb[i];
    out[OFF_NSUM + i] = ns;
    bool used = (ncnt >= 1.0f);
    float refreshed = ns / fmaxf(ncnt, 1e-8f);
    out[OFF_NCB + i] = used ? refreshed : x[i];
    if (d == 0) {
        out[OFF_NCNT + c] = ncnt;
        float p = cntb * (1.0f / 131072.0f);
        atomicAdd(&g_plog, p * logf(p + 1e-7f));
    }
}

// ---- K4: scalars ----
__global__ void k_scalars(float* __restrict__ out) {
    out[OFF_COMMIT] = g_commit * (1.0f / 8388608.0f);
    out[OFF_PERP]   = expf(-g_plog);
}

extern "C" void kernel_launch(void* const* d_in, const int* in_sizes, int n_in,
                              void* d_out, int out_size) {
    const float* x    = (const float*)d_in[0];
    const float* cb   = (const float*)d_in[1];
    const float* csum = (const float*)d_in[2];
    const float* ccnt = (const float*)d_in[3];
    float* out = (float*)d_out;

    k_zero<<<8, 256>>>();
    k_split_cb<<<8, 256>>>(cb);
    k1_scan<<<NTOK / 128, 256>>>(x);
    k_refine<<<NTOK / 8, 256>>>(x, cb);
    k_hist<<<NTOK / 256, 256>>>();
    k_prefix<<<1, 256>>>();
    k_place<<<NTOK / 256, 256>>>();
    k_sum<<<NCODE / 8, 256>>>(x, cb, out);
    k_final<<<NCODE * DIM / 256, 256>>>(x, csum, ccnt, out);
    k_scalars<<<1, 1>>>(out);
}

// round 16
// speedup vs baseline: 1.9971x; 1.9971x over previous
#include <cuda_runtime.h>
#include <cuda_fp16.h>
#include <math.h>
#include <stdint.h>

#define NTOK   131072
#define NCODE  2048
#define DIM    64
#define NCAND  32
#define MARGIN 8e-3f

// Output layout (tuple flattened):
#define OFF_XOUT   0
#define OFF_COMMIT 8388608
#define OFF_PERP   8388609
#define OFF_NCB    8388610
#define OFF_NSUM   8519682
#define OFF_NCNT   8650754

// ---- device scratch ----
__device__ int   g_idx[NTOK];
__device__ int   g_hist[NCODE];
__device__ int   g_start[NCODE];
__device__ int   g_cursor[NCODE];
__device__ int   g_tok[NTOK];
__device__ float g_cnorm[NCODE];
__device__ float g_sumb[NCODE * DIM];
__device__ float g_commit;
__device__ float g_plog;
__device__ __half g_ch[NCODE * DIM];
__device__ int   g_cand[(size_t)NTOK * NCAND];
__device__ float g_candt[(size_t)NTOK * NCAND];
__device__ int   g_candn[NTOK];
__device__ float g_tmin[NTOK];

__device__ __forceinline__ uint32_t smem_u32(const void* p) {
    uint32_t a;
    asm("{ .reg .u64 t; cvta.to.shared.u64 t, %1; cvt.u32.u64 %0, t; }" : "=r"(a) : "l"(p));
    return a;
}
#define LDX4(r, addr) \
    asm volatile("ldmatrix.sync.aligned.m8n8.x4.shared.b16 {%0,%1,%2,%3}, [%4];" \
        : "=r"((r)[0]), "=r"((r)[1]), "=r"((r)[2]), "=r"((r)[3]) : "r"(addr))

__device__ __forceinline__ void mma16816(float* c, const uint32_t* a, uint32_t b0, uint32_t b1) {
    asm volatile("mma.sync.aligned.m16n8k16.row.col.f32.f16.f16.f32 "
        "{%0,%1,%2,%3},{%4,%5,%6,%7},{%8,%9},{%0,%1,%2,%3};"
        : "+f"(c[0]), "+f"(c[1]), "+f"(c[2]), "+f"(c[3])
        : "r"(a[0]), "r"(a[1]), "r"(a[2]), "r"(a[3]), "r"(b0), "r"(b1));
}
__device__ __forceinline__ void cpa16(uint32_t dst, const void* src) {
    asm volatile("cp.async.cg.shared.global [%0], [%1], 16;" :: "r"(dst), "l"(src));
}
#define CPA_COMMIT() asm volatile("cp.async.commit_group;" ::: "memory")
#define CPA_WAIT1()  asm volatile("cp.async.wait_group 1;" ::: "memory")

union U8H { __half h[8]; uint4 u; };
union U4H { __half h[4]; uint2 u; };

// smem per buffer: bh[128 rows * 144B] + cns[128]f
#define OFF_CN 18432
#define BUFB   18944

// ---- K0: zero scalars + histogram ----
__global__ void k_zero() {
    int i = blockIdx.x * 256 + threadIdx.x;
    if (i < NCODE) g_hist[i] = 0;
    if (i == 0) { g_commit = 0.0f; g_plog = 0.0f; }
}

// ---- K0b: codebook fp16-high + ||c||^2 (reference rounding) ----
__global__ void k_split_cb(const float* __restrict__ cb) {
    int c = blockIdx.x * 256 + threadIdx.x;
    if (c >= NCODE) return;
    const float4* cp = (const float4*)(cb + (size_t)c * DIM);
    float cn = 0.0f;
#pragma unroll
    for (int q = 0; q < 8; q++) {
        float4 a = cp[2 * q], b = cp[2 * q + 1];
        float v[8] = {a.x, a.y, a.z, a.w, b.x, b.y, b.z, b.w};
        U8H H;
#pragma unroll
        for (int i = 0; i < 8; i++) {
            H.h[i] = __float2half_rn(v[i]);
            cn = __fadd_rn(cn, __fmul_rn(v[i], v[i]));
        }
        *(uint4*)&g_ch[(size_t)c * DIM + q * 8] = H.u;
    }
    g_cnorm[c] = cn;
}

// ---- K1: hh-only HMMA scan + two-phase candidate recording ----
__device__ __forceinline__ void prefetch_chunk(uint32_t bsm, int n0, int tid) {
#pragma unroll
    for (int i = tid; i < 1024; i += 256) {
        int r = i >> 3, j = i & 7;
        cpa16(bsm + r * 144 + j * 16, &g_ch[(size_t)(n0 + r) * DIM + j * 8]);
    }
    if (tid < 32) cpa16(bsm + OFF_CN + tid * 16, &g_cnorm[n0 + tid * 4]);
}

__global__ void __launch_bounds__(256, 2) k1_scan(const float* __restrict__ x) {
    __shared__ __align__(16) char buf[2 * BUFB];
    __shared__ int scnt[128];
    uint32_t sb = smem_u32(buf);
    int tid = threadIdx.x, w = tid >> 5, l = tid & 31;
    int g = l >> 3, lr = l & 7, gid = l >> 2, tig = l & 3;
    int m0 = blockIdx.x * 128;

    if (tid < 128) scnt[tid] = 0;

    // convert x rows to fp16-high into buf0 (stride 144)
    {
        int r = tid >> 1, seg = tid & 1;
        const float4* xp = (const float4*)(x + (size_t)(m0 + r) * DIM + seg * 32);
#pragma unroll
        for (int q = 0; q < 8; q++) {
            float4 v = xp[q];
            U4H H;
            H.h[0] = __float2half_rn(v.x); H.h[1] = __float2half_rn(v.y);
            H.h[2] = __float2half_rn(v.z); H.h[3] = __float2half_rn(v.w);
            *(uint2*)(buf + r * 144 + (seg * 32 + q * 4) * 2) = H.u;
        }
    }
    __syncthreads();

    uint32_t ah[4][4];
    {
        int arow = w * 16 + (g & 1) * 8 + lr;
#pragma unroll
        for (int kk = 0; kk < 4; kk++)
            LDX4(ah[kk], sb + arow * 144 + (kk * 16 + (g >> 1) * 8) * 2);
    }
    __syncthreads();

    int tokl0 = w * 16 + gid, tokl1 = tokl0 + 8;
    int tokg0 = m0 + tokl0, tokg1 = m0 + tokl1;
    float tmin0 = 3.4e38f, tmin1 = 3.4e38f;

    prefetch_chunk(sb, 0, tid);          CPA_COMMIT();
    prefetch_chunk(sb + BUFB, 128, tid); CPA_COMMIT();

    for (int c = 0; c < 16; c++) {
        uint32_t bb = sb + (c & 1) * BUFB;
        const float* cns = (const float*)(buf + (c & 1) * BUFB + OFF_CN);
        CPA_WAIT1();
        __syncthreads();

#pragma unroll
        for (int hf = 0; hf < 2; hf++) {
            float acc[8][4];
#pragma unroll
            for (int n = 0; n < 8; n++)
#pragma unroll
                for (int q = 0; q < 4; q++) acc[n][q] = 0.0f;

#pragma unroll
            for (int kk = 0; kk < 4; kk++) {
#pragma unroll
                for (int p = 0; p < 4; p++) {
                    int brow = hf * 64 + p * 16 + (g & 1) * 8 + lr;
                    uint32_t bh[4];
                    LDX4(bh, bb + brow * 144 + (kk * 16 + (g >> 1) * 8) * 2);
                    mma16816(acc[2 * p],     ah[kk], bh[0], bh[2]);
                    mma16816(acc[2 * p + 1], ah[kk], bh[1], bh[3]);
                }
            }
            // Phase A: convert to t = cn - 2*dot (in place), find block min
            float lmin0 = 3.4e38f, lmin1 = 3.4e38f;
#pragma unroll
            for (int nt = 0; nt < 8; nt++) {
                int nl = hf * 64 + nt * 8 + 2 * tig;
                float cn0 = cns[nl], cn1 = cns[nl + 1];
                float t0 = __fmaf_rn(-2.0f, acc[nt][0], cn0);
                float t1 = __fmaf_rn(-2.0f, acc[nt][1], cn1);
                float t2 = __fmaf_rn(-2.0f, acc[nt][2], cn0);
                float t3 = __fmaf_rn(-2.0f, acc[nt][3], cn1);
                acc[nt][0] = t0; acc[nt][1] = t1; acc[nt][2] = t2; acc[nt][3] = t3;
                lmin0 = fminf(lmin0, fminf(t0, t1));
                lmin1 = fminf(lmin1, fminf(t2, t3));
            }
#pragma unroll
            for (int off = 1; off <= 2; off <<= 1) {
                lmin0 = fminf(lmin0, __shfl_xor_sync(0xffffffffu, lmin0, off));
                lmin1 = fminf(lmin1, __shfl_xor_sync(0xffffffffu, lmin1, off));
            }
            tmin0 = fminf(tmin0, lmin0);
            tmin1 = fminf(tmin1, lmin1);
            float thr0 = tmin0 + MARGIN, thr1 = tmin1 + MARGIN;

            // Phase B: record candidates under the settled threshold
#pragma unroll
            for (int nt = 0; nt < 8; nt++) {
                float t0 = acc[nt][0], t1 = acc[nt][1];
                float t2 = acc[nt][2], t3 = acc[nt][3];
                bool p = (t0 < thr0) | (t1 < thr0) | (t2 < thr1) | (t3 < thr1);
                if (__any_sync(0xffffffffu, p)) {
                    int ci = c * 128 + hf * 64 + nt * 8 + 2 * tig;
                    if (t0 < thr0) {
                        int pos = atomicAdd(&scnt[tokl0], 1);
                        if (pos < NCAND) { g_cand[(size_t)tokg0 * NCAND + pos] = ci;
                                           g_candt[(size_t)tokg0 * NCAND + pos] = t0; }
                    }
                    if (t1 < thr0) {
                        int pos = atomicAdd(&scnt[tokl0], 1);
                        if (pos < NCAND) { g_cand[(size_t)tokg0 * NCAND + pos] = ci + 1;
                                           g_candt[(size_t)tokg0 * NCAND + pos] = t1; }
                    }
                    if (t2 < thr1) {
                        int pos = atomicAdd(&scnt[tokl1], 1);
                        if (pos < NCAND) { g_cand[(size_t)tokg1 * NCAND + pos] = ci;
                                           g_candt[(size_t)tokg1 * NCAND + pos] = t2; }
                    }
                    if (t3 < thr1) {
                        int pos = atomicAdd(&scnt[tokl1], 1);
                        if (pos < NCAND) { g_cand[(size_t)tokg1 * NCAND + pos] = ci + 1;
                                           g_candt[(size_t)tokg1 * NCAND + pos] = t3; }
                    }
                }
            }
        }
        __syncthreads();
        if (c + 2 < 16) prefetch_chunk(bb, (c + 2) * 128, tid);
        CPA_COMMIT();
    }

    if (tig == 0) {
        g_tmin[tokg0]  = tmin0;
        g_tmin[tokg1]  = tmin1;
        g_candn[tokg0] = scnt[tokl0];
        g_candn[tokg1] = scnt[tokl1];
    }
}

// ---- K1b: exact refinement (1 warp per token) + histogram ----
__global__ void k_refine(const float* __restrict__ x, const float* __restrict__ cb) {
    int t = blockIdx.x * 8 + (threadIdx.x >> 5);
    int l = threadIdx.x & 31;
    int n = g_candn[t];
    float tmin = g_tmin[t];

    float2 xv = *(const float2*)(x + (size_t)t * DIM + l * 2);
    float lxn = __fadd_rn(__fmul_rn(xv.x, xv.x), __fmul_rn(xv.y, xv.y));
#pragma unroll
    for (int o = 16; o; o >>= 1) lxn += __shfl_xor_sync(0xffffffffu, lxn, o);
    float xn = lxn;

    float bv = 3.4e38f;
    int bi = NCODE;

    if (n <= NCAND) {
        for (int i = 0; i < n; i++) {
            float tv = g_candt[(size_t)t * NCAND + i];
            if (tv <= tmin + MARGIN) {
                int ci = g_cand[(size_t)t * NCAND + i];
                float2 cv = *(const float2*)(cb + (size_t)ci * DIM + l * 2);
                float d = __fmaf_rn(xv.y, cv.y, __fmul_rn(xv.x, cv.x));
#pragma unroll
                for (int o = 16; o; o >>= 1) d += __shfl_xor_sync(0xffffffffu, d, o);
                float s = __fadd_rn(__fsub_rn(xn, __fmul_rn(2.0f, d)), g_cnorm[ci]);
                if (s < bv || (s == bv && ci < bi)) { bv = s; bi = ci; }
            }
        }
    } else {
        for (int ci = 0; ci < NCODE; ci++) {
            float2 cv = *(const float2*)(cb + (size_t)ci * DIM + l * 2);
            float d = __fmaf_rn(xv.y, cv.y, __fmul_rn(xv.x, cv.x));
#pragma unroll
            for (int o = 16; o; o >>= 1) d += __shfl_xor_sync(0xffffffffu, d, o);
            float s = __fadd_rn(__fsub_rn(xn, __fmul_rn(2.0f, d)), g_cnorm[ci]);
            if (s < bv) { bv = s; bi = ci; }
        }
    }
    if (l == 0) {
        g_idx[t] = bi;
        atomicAdd(&g_hist[bi], 1);
    }
}

// ---- K2b: exclusive prefix scan (1 block) ----
__global__ void k_prefix() {
    __shared__ int warpsum[8];
    int tid = threadIdx.x, lane = tid & 31, wid = tid >> 5;
    int loc[8], s = 0;
#pragma unroll
    for (int j = 0; j < 8; j++) { loc[j] = s; s += g_hist[tid * 8 + j]; }
    int v = s;
#pragma unroll
    for (int off = 1; off < 32; off <<= 1) {
        int t = __shfl_up_sync(0xffffffffu, v, off);
        if (lane >= off) v += t;
    }
    if (lane == 31) warpsum[wid] = v;
    __syncthreads();
    if (wid == 0) {
        int wv = (lane < 8) ? warpsum[lane] : 0;
#pragma unroll
        for (int off = 1; off < 8; off <<= 1) {
            int t = __shfl_up_sync(0xffffffffu, wv, off);
            if (lane >= off) wv += t;
        }
        if (lane < 8) warpsum[lane] = wv;
    }
    __syncthreads();
    int base = ((wid > 0) ? warpsum[wid - 1] : 0) + (v - s);
#pragma unroll
    for (int j = 0; j < 8; j++) {
        g_start[tid * 8 + j]  = base + loc[j];
        g_cursor[tid * 8 + j] = base + loc[j];
    }
}

// ---- K2c: place tokens in code order ----
__global__ void k_place() {
    int t = blockIdx.x * 256 + threadIdx.x;
    int pos = atomicAdd(&g_cursor[g_idx[t]], 1);
    g_tok[pos] = t;
}

// ---- K2d: per-code gather-sum: code_sum_batch, x_out, commit ----
__global__ void k_sum(const float* __restrict__ x, const float* __restrict__ cb,
                      float* __restrict__ out) {
    int wid = threadIdx.x >> 5, l = threadIdx.x & 31;
    int c = blockIdx.x * 8 + wid;
    int d0 = l * 2;
    float cv0 = cb[(size_t)c * DIM + d0], cv1 = cb[(size_t)c * DIM + d0 + 1];
    int beg = g_start[c], n = g_hist[c];
    float s0 = 0.0f, s1 = 0.0f, cs = 0.0f;
    for (int i = 0; i < n; i++) {
        int t = g_tok[beg + i];
        float2 xv = *(const float2*)(x + (size_t)t * DIM + d0);
        float2 o;
        o.x = __fadd_rn(xv.x, __fsub_rn(cv0, xv.x));
        o.y = __fadd_rn(xv.y, __fsub_rn(cv1, xv.y));
        *(float2*)(out + OFF_XOUT + (size_t)t * DIM + d0) = o;
        s0 += xv.x; s1 += xv.y;
        float dx = __fsub_rn(xv.x, cv0), dy = __fsub_rn(xv.y, cv1);
        cs += dx * dx + dy * dy;
    }
    g_sumb[(size_t)c * DIM + d0]     = s0;
    g_sumb[(size_t)c * DIM + d0 + 1] = s1;
#pragma unroll
    for (int o = 16; o; o >>= 1) cs += __shfl_xor_sync(0xffffffffu, cs, o);
    if (l == 0) atomicAdd(&g_commit, cs);
}

// ---- K3: EMA update, new codebook, perplexity partials ----
__global__ void k_final(const float* __restrict__ x, const float* __restrict__ code_sum,
                        const float* __restrict__ code_count, float* __restrict__ out) {
    int i = blockIdx.x * 256 + threadIdx.x;
    int c = i >> 6, d = i & 63;
    float cntb = (float)g_hist[c];
    float ncnt = 0.99f * code_count[c] + 0.01f * cntb;
    float ns = 0.99f * code_sum[i] + 0.01f * g_sumb[i];
    out[OFF_NSUM + i] = ns;
    bool used = (ncnt >= 1.0f);
    float refreshed = ns / fmaxf(ncnt, 1e-8f);
    out[OFF_NCB + i] = used ? refreshed : x[i];
    if (d == 0) {
        out[OFF_NCNT + c] = ncnt;
        float p = cntb * (1.0f / 131072.0f);
        atomicAdd(&g_plog, p * logf(p + 1e-7f));
    }
}

// ---- K4: scalars ----
__global__ void k_scalars(float* __restrict__ out) {
    out[OFF_COMMIT] = g_commit * (1.0f / 8388608.0f);
    out[OFF_PERP]   = expf(-g_plog);
}

extern "C" void kernel_launch(void* const* d_in, const int* in_sizes, int n_in,
                              void* d_out, int out_size) {
    const float* x    = (const float*)d_in[0];
    const float* cb   = (const float*)d_in[1];
    const float* csum = (const float*)d_in[2];
    const float* ccnt = (const float*)d_in[3];
    float* out = (float*)d_out;

    k_zero<<<8, 256>>>();
    k_split_cb<<<8, 256>>>(cb);
    k1_scan<<<NTOK / 128, 256>>>(x);
    k_refine<<<NTOK / 8, 256>>>(x, cb);
    k_prefix<<<1, 256>>>();
    k_place<<<NTOK / 256, 256>>>();
    k_sum<<<NCODE / 8, 256>>>(x, cb, out);
    k_final<<<NCODE * DIM / 256, 256>>>(x, csum, ccnt, out);
    k_scalars<<<1, 1>>>(out);
}